// round 1
// baseline (speedup 1.0000x reference)
#include <cuda_runtime.h>
#include <math.h>
#include <stdint.h>

// Problem dims (fixed by the reference)
#define SEQ    2048
#define BATCH  32
#define DIM    1024
#define M_TOT  (SEQ * BATCH)     // 65536
#define N_TOT  (3 * DIM)         // 3072
#define K_TOT  DIM               // 1024

// Scratch for activated gates: [M_TOT][N_TOT] fp32 = 768 MB.
// __device__ global (module-load allocation) — allowed; no cudaMalloc.
__device__ float g_act[(size_t)M_TOT * N_TOT];

// ---------------------------------------------------------------------------
// Kernel 1: C = X @ W^T + b, fused activation, write to g_act.
//   X: [M_TOT, K_TOT] row-major      (K contiguous)
//   W: [N_TOT, K_TOT] row-major      (K contiguous)  -> TN dot products
//   activation: n <  DIM  -> tanh
//               n >= DIM  -> sigmoid (both F and O gates)
// Tile: BM=128, BN=128, BK=16, 256 threads, 8x8 per-thread micro-tile,
// double-buffered shared memory.
// ---------------------------------------------------------------------------
#define BM 128
#define BN 128
#define BK 16
#define SSTRIDE 132   // BM + 4 padding, keeps float4 alignment

__global__ __launch_bounds__(256, 2)
void gemm_act_kernel(const float* __restrict__ X,
                     const float* __restrict__ W,
                     const float* __restrict__ b)
{
    __shared__ float As[2][BK][SSTRIDE];
    __shared__ float Bs[2][BK][SSTRIDE];

    const int tid = threadIdx.x;
    const int tx  = tid & 15;          // n direction (0..15)
    const int ty  = tid >> 4;          // m direction (0..15)

    const int block_m = blockIdx.y * BM;
    const int block_n = blockIdx.x * BN;

    const float* Aptr = X + (size_t)block_m * K_TOT;
    const float* Wptr = W + (size_t)block_n * K_TOT;

    float acc[8][8];
#pragma unroll
    for (int i = 0; i < 8; ++i)
#pragma unroll
        for (int j = 0; j < 8; ++j) acc[i][j] = 0.0f;

    // Per-thread global-load coordinates: tile is 128 rows x 4 float4 per row
    // = 512 float4; each thread handles 2 (positions tid and tid+256).
    const int pos0 = tid;
    const int pos1 = tid + 256;
    const int row0 = pos0 >> 2, c40 = pos0 & 3;
    const int row1 = pos1 >> 2, c41 = pos1 & 3;

    float4 ra0, ra1, rw0, rw1;

    // ---- prologue: load tile 0 ----
    {
        const int k0 = 0;
        ra0 = *(const float4*)(Aptr + (size_t)row0 * K_TOT + k0 + c40 * 4);
        ra1 = *(const float4*)(Aptr + (size_t)row1 * K_TOT + k0 + c41 * 4);
        rw0 = *(const float4*)(Wptr + (size_t)row0 * K_TOT + k0 + c40 * 4);
        rw1 = *(const float4*)(Wptr + (size_t)row1 * K_TOT + k0 + c41 * 4);

        As[0][c40 * 4 + 0][row0] = ra0.x;
        As[0][c40 * 4 + 1][row0] = ra0.y;
        As[0][c40 * 4 + 2][row0] = ra0.z;
        As[0][c40 * 4 + 3][row0] = ra0.w;
        As[0][c41 * 4 + 0][row1] = ra1.x;
        As[0][c41 * 4 + 1][row1] = ra1.y;
        As[0][c41 * 4 + 2][row1] = ra1.z;
        As[0][c41 * 4 + 3][row1] = ra1.w;

        Bs[0][c40 * 4 + 0][row0] = rw0.x;
        Bs[0][c40 * 4 + 1][row0] = rw0.y;
        Bs[0][c40 * 4 + 2][row0] = rw0.z;
        Bs[0][c40 * 4 + 3][row0] = rw0.w;
        Bs[0][c41 * 4 + 0][row1] = rw1.x;
        Bs[0][c41 * 4 + 1][row1] = rw1.y;
        Bs[0][c41 * 4 + 2][row1] = rw1.z;
        Bs[0][c41 * 4 + 3][row1] = rw1.w;
    }
    __syncthreads();

    const int nTiles = K_TOT / BK;   // 64
    for (int t = 0; t < nTiles; ++t) {
        const int buf = t & 1;

        // prefetch next tile to registers
        if (t + 1 < nTiles) {
            const int k0 = (t + 1) * BK;
            ra0 = *(const float4*)(Aptr + (size_t)row0 * K_TOT + k0 + c40 * 4);
            ra1 = *(const float4*)(Aptr + (size_t)row1 * K_TOT + k0 + c41 * 4);
            rw0 = *(const float4*)(Wptr + (size_t)row0 * K_TOT + k0 + c40 * 4);
            rw1 = *(const float4*)(Wptr + (size_t)row1 * K_TOT + k0 + c41 * 4);
        }

        // compute on current buffer
#pragma unroll
        for (int kk = 0; kk < BK; ++kk) {
            float a[8], w[8];
            float4 av0 = *(const float4*)&As[buf][kk][ty * 8 + 0];
            float4 av1 = *(const float4*)&As[buf][kk][ty * 8 + 4];
            float4 wv0 = *(const float4*)&Bs[buf][kk][tx * 8 + 0];
            float4 wv1 = *(const float4*)&Bs[buf][kk][tx * 8 + 4];
            a[0]=av0.x; a[1]=av0.y; a[2]=av0.z; a[3]=av0.w;
            a[4]=av1.x; a[5]=av1.y; a[6]=av1.z; a[7]=av1.w;
            w[0]=wv0.x; w[1]=wv0.y; w[2]=wv0.z; w[3]=wv0.w;
            w[4]=wv1.x; w[5]=wv1.y; w[6]=wv1.z; w[7]=wv1.w;
#pragma unroll
            for (int i = 0; i < 8; ++i)
#pragma unroll
                for (int j = 0; j < 8; ++j)
                    acc[i][j] = fmaf(a[i], w[j], acc[i][j]);
        }

        // stage next tile into the other buffer
        if (t + 1 < nTiles) {
            const int nb = (t + 1) & 1;
            As[nb][c40 * 4 + 0][row0] = ra0.x;
            As[nb][c40 * 4 + 1][row0] = ra0.y;
            As[nb][c40 * 4 + 2][row0] = ra0.z;
            As[nb][c40 * 4 + 3][row0] = ra0.w;
            As[nb][c41 * 4 + 0][row1] = ra1.x;
            As[nb][c41 * 4 + 1][row1] = ra1.y;
            As[nb][c41 * 4 + 2][row1] = ra1.z;
            As[nb][c41 * 4 + 3][row1] = ra1.w;

            Bs[nb][c40 * 4 + 0][row0] = rw0.x;
            Bs[nb][c40 * 4 + 1][row0] = rw0.y;
            Bs[nb][c40 * 4 + 2][row0] = rw0.z;
            Bs[nb][c40 * 4 + 3][row0] = rw0.w;
            Bs[nb][c41 * 4 + 0][row1] = rw1.x;
            Bs[nb][c41 * 4 + 1][row1] = rw1.y;
            Bs[nb][c41 * 4 + 2][row1] = rw1.z;
            Bs[nb][c41 * 4 + 3][row1] = rw1.w;
        }
        __syncthreads();
    }

    // ---- epilogue: bias + activation, write to scratch ----
    // All n in this block are in one gate region (DIM is a multiple of BN).
    const bool is_tanh = (block_n < DIM);
    const int mbase = block_m + ty * 8;
    const int nbase = block_n + tx * 8;

#pragma unroll
    for (int i = 0; i < 8; ++i) {
        float* dst = &g_act[(size_t)(mbase + i) * N_TOT + nbase];
#pragma unroll
        for (int j = 0; j < 8; ++j) {
            float v = acc[i][j] + b[nbase + j];
            float act;
            if (is_tanh) {
                act = tanhf(v);
            } else {
                act = 1.0f / (1.0f + __expf(-v));
            }
            dst[j] = act;
        }
    }
}

// ---------------------------------------------------------------------------
// Kernel 2: sequential scan over SEQ for each of the 32768 (batch, d) chains.
//   h = f*h + (1-f)*z  (= fma(f, h-z, z));  H[s,b,d] = o * h;  h_n = h(final)
// Gate layout in g_act row (s*BATCH+b): [0,DIM)=tanh(Z), [DIM,2DIM)=sig(F),
// [2DIM,3DIM)=sig(O).
// ---------------------------------------------------------------------------
__global__ __launch_bounds__(256)
void scan_kernel(const float* __restrict__ hidden, float* __restrict__ out)
{
    const int t = blockIdx.x * blockDim.x + threadIdx.x;  // 0..32767
    const int bb = t >> 10;          // batch index
    const int d  = t & 1023;         // feature index

    float h = hidden[bb * DIM + d];

    float* __restrict__ Hout = out;
    float* __restrict__ hn   = out + (size_t)SEQ * BATCH * DIM;

#pragma unroll 4
    for (int s = 0; s < SEQ; ++s) {
        const size_t row = (size_t)(s * BATCH + bb) * N_TOT;
        const float z = g_act[row + d];
        const float f = g_act[row + DIM + d];
        const float o = g_act[row + 2 * DIM + d];
        h = fmaf(f, h - z, z);               // f*h + (1-f)*z
        Hout[(size_t)(s * BATCH + bb) * DIM + d] = o * h;
    }
    hn[bb * DIM + d] = h;
}

// ---------------------------------------------------------------------------
extern "C" void kernel_launch(void* const* d_in, const int* in_sizes, int n_in,
                              void* d_out, int out_size)
{
    const float* X      = (const float*)d_in[0];   // [2048, 32, 1024]
    const float* hidden = (const float*)d_in[1];   // [1, 32, 1024]
    const float* W      = (const float*)d_in[2];   // [3072, 1024]
    const float* b      = (const float*)d_in[3];   // [3072]
    float* out = (float*)d_out;                    // H ‖ h_n

    dim3 grid(N_TOT / BN, M_TOT / BM);             // (24, 512)
    gemm_act_kernel<<<grid, 256>>>(X, W, b);

    scan_kernel<<<(BATCH * DIM) / 256, 256>>>(hidden, out);
}

// round 3
// speedup vs baseline: 1.9682x; 1.9682x over previous
#include <cuda_runtime.h>
#include <math.h>
#include <stdint.h>

// ---------------------------------------------------------------------------
// Problem dims (fixed by the reference)
// ---------------------------------------------------------------------------
#define SEQ    2048
#define BATCH  32
#define DIM    1024
#define M_TOT  (SEQ * BATCH)     // 65536
#define N_TOT  (3 * DIM)         // 3072
#define K_TOT  DIM               // 1024

// GEMM tile
#define BM 128
#define BN 128
#define BK 16
#define NCHUNK (K_TOT / BK)      // 64
#define ASTRIDE 20               // padded floats per row: banks (20*q+4*r)%32 and
                                 // (4*q+r)%32 are all-distinct -> conflict-free

// Scratch (device global; no cudaMalloc allowed): activated gates, 768 MB
__device__ float g_act[(size_t)M_TOT * N_TOT];

// ---------------------------------------------------------------------------
// Helpers
// ---------------------------------------------------------------------------
__device__ __forceinline__ uint32_t tf32_rna(float x) {
    uint32_t r; asm("cvt.rna.tf32.f32 %0, %1;" : "=r"(r) : "f"(x)); return r;
}
__device__ __forceinline__ float rcp_fast(float x) {
    float r; asm("rcp.approx.f32 %0, %1;" : "=f"(r) : "f"(x)); return r;
}
__device__ __forceinline__ float sigmoid_f(float x) {
    return rcp_fast(1.0f + __expf(-x));
}
__device__ __forceinline__ float tanh_f(float x) {
    return 1.0f - 2.0f * rcp_fast(1.0f + __expf(2.0f * x));
}

// m16n8k8 tf32 HMMA (portable PTX, legal at compute_103)
__device__ __forceinline__ void mma_tf32(float* d,
                                         const uint32_t* a,
                                         const uint32_t* bb) {
    asm volatile(
        "mma.sync.aligned.m16n8k8.row.col.f32.tf32.tf32.f32 "
        "{%0,%1,%2,%3}, {%4,%5,%6,%7}, {%8,%9}, {%0,%1,%2,%3};\n"
        : "+f"(d[0]), "+f"(d[1]), "+f"(d[2]), "+f"(d[3])
        : "r"(a[0]), "r"(a[1]), "r"(a[2]), "r"(a[3]),
          "r"(bb[0]), "r"(bb[1]));
}

// ---------------------------------------------------------------------------
// Kernel 1: HMMA tf32 GEMM, C = X @ W^T + b, fused activation -> g_act
//   256 threads = 8 warps in a 2(M) x 4(N) grid; warp tile 64x32;
//   each warp: 4x4 grid of m16n8k8 MMAs per k-step (BK=16 -> 2 ksteps/chunk).
//   Inputs rounded to tf32 (rna) in registers during SMEM staging.
// ---------------------------------------------------------------------------
__global__ __launch_bounds__(256, 2)
void gemm_hmma_kernel(const float* __restrict__ X,
                      const float* __restrict__ W,
                      const float* __restrict__ b)
{
    __shared__ float As[2][BM * ASTRIDE];   // 2 x 10240 B
    __shared__ float Bs[2][BN * ASTRIDE];   // 2 x 10240 B

    const int tid = threadIdx.x;
    const int wid = tid >> 5;
    const int lid = tid & 31;
    const int lq  = lid >> 2;   // 0..7
    const int lr  = lid & 3;    // 0..3

    const int wm = (wid >> 2) * 64;   // warp M offset: 0 / 64
    const int wn = (wid & 3) * 32;    // warp N offset: 0..96

    const int block_m = blockIdx.y * BM;
    const int block_n = blockIdx.x * BN;

    const float* Abase = X + (size_t)block_m * K_TOT;
    const float* Bbase = W + (size_t)block_n * K_TOT;

    float acc[4][4][4];
#pragma unroll
    for (int mt = 0; mt < 4; ++mt)
#pragma unroll
        for (int nt = 0; nt < 4; ++nt)
#pragma unroll
            for (int r = 0; r < 4; ++r) acc[mt][nt][r] = 0.0f;

    // staging coordinates: chunk is 128 rows x 4 float4 = 512 float4;
    // each of 256 threads handles 2 (per matrix).
    const int row0 = tid >> 1;                 // 0..127
    const int c40  = (tid & 1);                // float4 col 0..1
    // second element: +2 in float4 col
    // layout: (row, c4) with c4 in 0..3 ; thread covers (row0, c40) and (row0, c40+2)

    float4 ra0, ra1, rb0, rb1;

    // ---- prologue: load chunk 0 ----
    {
        ra0 = *(const float4*)(Abase + (size_t)row0 * K_TOT + (c40 + 0) * 4);
        ra1 = *(const float4*)(Abase + (size_t)row0 * K_TOT + (c40 + 2) * 4);
        rb0 = *(const float4*)(Bbase + (size_t)row0 * K_TOT + (c40 + 0) * 4);
        rb1 = *(const float4*)(Bbase + (size_t)row0 * K_TOT + (c40 + 2) * 4);

        uint32_t* a = (uint32_t*)As[0];
        uint32_t* bsh = (uint32_t*)Bs[0];
        int o0 = row0 * ASTRIDE + c40 * 4;
        int o1 = row0 * ASTRIDE + (c40 + 2) * 4;
        a[o0+0]=tf32_rna(ra0.x); a[o0+1]=tf32_rna(ra0.y); a[o0+2]=tf32_rna(ra0.z); a[o0+3]=tf32_rna(ra0.w);
        a[o1+0]=tf32_rna(ra1.x); a[o1+1]=tf32_rna(ra1.y); a[o1+2]=tf32_rna(ra1.z); a[o1+3]=tf32_rna(ra1.w);
        bsh[o0+0]=tf32_rna(rb0.x); bsh[o0+1]=tf32_rna(rb0.y); bsh[o0+2]=tf32_rna(rb0.z); bsh[o0+3]=tf32_rna(rb0.w);
        bsh[o1+0]=tf32_rna(rb1.x); bsh[o1+1]=tf32_rna(rb1.y); bsh[o1+2]=tf32_rna(rb1.z); bsh[o1+3]=tf32_rna(rb1.w);
    }
    __syncthreads();

    for (int c = 0; c < NCHUNK; ++c) {
        const int buf = c & 1;

        // prefetch next chunk into registers
        if (c + 1 < NCHUNK) {
            const int kcol = (c + 1) * BK;
            ra0 = *(const float4*)(Abase + (size_t)row0 * K_TOT + kcol + (c40 + 0) * 4);
            ra1 = *(const float4*)(Abase + (size_t)row0 * K_TOT + kcol + (c40 + 2) * 4);
            rb0 = *(const float4*)(Bbase + (size_t)row0 * K_TOT + kcol + (c40 + 0) * 4);
            rb1 = *(const float4*)(Bbase + (size_t)row0 * K_TOT + kcol + (c40 + 2) * 4);
        }

        // compute 2 k-steps on current buffer
        const uint32_t* Ab = (const uint32_t*)As[buf];
        const uint32_t* Bb = (const uint32_t*)Bs[buf];
#pragma unroll
        for (int ks = 0; ks < 2; ++ks) {
            const int k0 = ks * 8;
            uint32_t afrag[4][4], bfrag[4][2];
#pragma unroll
            for (int mt = 0; mt < 4; ++mt) {
                int base = (wm + mt * 16 + lq) * ASTRIDE + k0 + lr;
                afrag[mt][0] = Ab[base];
                afrag[mt][1] = Ab[base + 8 * ASTRIDE];
                afrag[mt][2] = Ab[base + 4];
                afrag[mt][3] = Ab[base + 8 * ASTRIDE + 4];
            }
#pragma unroll
            for (int nt = 0; nt < 4; ++nt) {
                int base = (wn + nt * 8 + lq) * ASTRIDE + k0 + lr;
                bfrag[nt][0] = Bb[base];
                bfrag[nt][1] = Bb[base + 4];
            }
#pragma unroll
            for (int mt = 0; mt < 4; ++mt)
#pragma unroll
                for (int nt = 0; nt < 4; ++nt)
                    mma_tf32(acc[mt][nt], afrag[mt], bfrag[nt]);
        }

        // stage prefetched chunk into the other buffer
        if (c + 1 < NCHUNK) {
            const int nb = buf ^ 1;
            uint32_t* a = (uint32_t*)As[nb];
            uint32_t* bsh = (uint32_t*)Bs[nb];
            int o0 = row0 * ASTRIDE + c40 * 4;
            int o1 = row0 * ASTRIDE + (c40 + 2) * 4;
            a[o0+0]=tf32_rna(ra0.x); a[o0+1]=tf32_rna(ra0.y); a[o0+2]=tf32_rna(ra0.z); a[o0+3]=tf32_rna(ra0.w);
            a[o1+0]=tf32_rna(ra1.x); a[o1+1]=tf32_rna(ra1.y); a[o1+2]=tf32_rna(ra1.z); a[o1+3]=tf32_rna(ra1.w);
            bsh[o0+0]=tf32_rna(rb0.x); bsh[o0+1]=tf32_rna(rb0.y); bsh[o0+2]=tf32_rna(rb0.z); bsh[o0+3]=tf32_rna(rb0.w);
            bsh[o1+0]=tf32_rna(rb1.x); bsh[o1+1]=tf32_rna(rb1.y); bsh[o1+2]=tf32_rna(rb1.z); bsh[o1+3]=tf32_rna(rb1.w);
        }
        __syncthreads();
    }

    // ---- epilogue: bias + activation, write to g_act ----
    const bool is_tanh = (block_n < DIM);   // BN=128 divides DIM; uniform per block

#pragma unroll
    for (int nt = 0; nt < 4; ++nt) {
        const int gc = block_n + wn + nt * 8 + 2 * lr;
        const float b0 = __ldg(&b[gc]);
        const float b1 = __ldg(&b[gc + 1]);
#pragma unroll
        for (int mt = 0; mt < 4; ++mt) {
            const int gm0 = block_m + wm + mt * 16 + lq;
            const int gm1 = gm0 + 8;
            float v00 = acc[mt][nt][0] + b0;
            float v01 = acc[mt][nt][1] + b1;
            float v10 = acc[mt][nt][2] + b0;
            float v11 = acc[mt][nt][3] + b1;
            float2 r0, r1;
            if (is_tanh) {
                r0.x = tanh_f(v00); r0.y = tanh_f(v01);
                r1.x = tanh_f(v10); r1.y = tanh_f(v11);
            } else {
                r0.x = sigmoid_f(v00); r0.y = sigmoid_f(v01);
                r1.x = sigmoid_f(v10); r1.y = sigmoid_f(v11);
            }
            *(float2*)(&g_act[(size_t)gm0 * N_TOT + gc]) = r0;
            *(float2*)(&g_act[(size_t)gm1 * N_TOT + gc]) = r1;
        }
    }
}

// ---------------------------------------------------------------------------
// Kernel 2: sequential scan (known-good)
// ---------------------------------------------------------------------------
__global__ __launch_bounds__(256)
void scan_kernel(const float* __restrict__ hidden, float* __restrict__ out)
{
    const int t = blockIdx.x * blockDim.x + threadIdx.x;  // 0..32767
    const int bb = t >> 10;
    const int d  = t & 1023;

    float h = hidden[bb * DIM + d];

    float* __restrict__ Hout = out;
    float* __restrict__ hn   = out + (size_t)SEQ * BATCH * DIM;

#pragma unroll 8
    for (int s = 0; s < SEQ; ++s) {
        const size_t row = (size_t)(s * BATCH + bb) * N_TOT;
        const float z = g_act[row + d];
        const float f = g_act[row + DIM + d];
        const float o = g_act[row + 2 * DIM + d];
        h = fmaf(f, h - z, z);
        Hout[(size_t)(s * BATCH + bb) * DIM + d] = o * h;
    }
    hn[bb * DIM + d] = h;
}

// ---------------------------------------------------------------------------
extern "C" void kernel_launch(void* const* d_in, const int* in_sizes, int n_in,
                              void* d_out, int out_size)
{
    const float* X      = (const float*)d_in[0];   // [2048, 32, 1024]
    const float* hidden = (const float*)d_in[1];   // [1, 32, 1024]
    const float* W      = (const float*)d_in[2];   // [3072, 1024]
    const float* b      = (const float*)d_in[3];   // [3072]
    float* out = (float*)d_out;

    dim3 grid(N_TOT / BN, M_TOT / BM);   // (24, 512)
    gemm_hmma_kernel<<<grid, 256>>>(X, W, b);

    scan_kernel<<<(BATCH * DIM) / 256, 256>>>(hidden, out);
}

// round 4
// speedup vs baseline: 2.6544x; 1.3487x over previous
#include <cuda_runtime.h>
#include <math.h>
#include <stdint.h>

// ---------------------------------------------------------------------------
// Problem dims (fixed by the reference)
// ---------------------------------------------------------------------------
#define SEQ    2048
#define BATCH  32
#define DIM    1024
#define M_TOT  (SEQ * BATCH)     // 65536
#define N_TOT  (3 * DIM)         // 3072
#define K_TOT  DIM               // 1024

// GEMM tile
#define BM 128
#define BN 256
#define BK 32
#define NCHUNK (K_TOT / BK)      // 32
#define NSTAGE 3
#define ASTRIDE 36               // floats per SMEM row (32 + 4 pad): LDS banks
                                 // (36q + r)%32 = (4q+r)%32 all-distinct

// SMEM layout (bytes)
#define A_STG_BYTES (BM * ASTRIDE * 4)          // 18432
#define B_STG_BYTES (BN * ASTRIDE * 4)          // 36864
#define SMEM_B_BASE (NSTAGE * A_STG_BYTES)      // 55296
#define SMEM_BYTES  (SMEM_B_BASE + NSTAGE * B_STG_BYTES)  // 165888

// Scratch (device globals; no cudaMalloc allowed)
__device__ float g_act[(size_t)M_TOT * N_TOT];   // 768 MB activated gates
__device__ float g_Xr[(size_t)M_TOT * K_TOT];    // 256 MB tf32-rounded X
__device__ float g_Wr[(size_t)N_TOT * K_TOT];    // 12  MB tf32-rounded W

// ---------------------------------------------------------------------------
// Helpers
// ---------------------------------------------------------------------------
__device__ __forceinline__ uint32_t smem_u32(const void* p) {
    uint32_t a;
    asm("{ .reg .u64 t; cvta.to.shared.u64 t, %1; cvt.u32.u64 %0, t; }"
        : "=r"(a) : "l"(p));
    return a;
}
__device__ __forceinline__ uint32_t tf32_rna(float x) {
    uint32_t r; asm("cvt.rna.tf32.f32 %0, %1;" : "=r"(r) : "f"(x)); return r;
}
__device__ __forceinline__ float rcp_fast(float x) {
    float r; asm("rcp.approx.f32 %0, %1;" : "=f"(r) : "f"(x)); return r;
}
__device__ __forceinline__ float sigmoid_f(float x) {
    return rcp_fast(1.0f + __expf(-x));
}
__device__ __forceinline__ float tanh_f(float x) {
    return 1.0f - 2.0f * rcp_fast(1.0f + __expf(2.0f * x));
}

__device__ __forceinline__ void cp_async16(uint32_t dst_smem, const void* src) {
    asm volatile("cp.async.cg.shared.global [%0], [%1], 16;"
                 :: "r"(dst_smem), "l"(src) : "memory");
}
__device__ __forceinline__ void cp_commit() {
    asm volatile("cp.async.commit_group;" ::: "memory");
}
template <int N>
__device__ __forceinline__ void cp_wait() {
    asm volatile("cp.async.wait_group %0;" :: "n"(N) : "memory");
}

// m16n8k8 tf32 HMMA (portable PTX, legal at compute_103)
__device__ __forceinline__ void mma_tf32(float* d,
                                         const uint32_t* a,
                                         const uint32_t* bb) {
    asm volatile(
        "mma.sync.aligned.m16n8k8.row.col.f32.tf32.tf32.f32 "
        "{%0,%1,%2,%3}, {%4,%5,%6,%7}, {%8,%9}, {%0,%1,%2,%3};\n"
        : "+f"(d[0]), "+f"(d[1]), "+f"(d[2]), "+f"(d[3])
        : "r"(a[0]), "r"(a[1]), "r"(a[2]), "r"(a[3]),
          "r"(bb[0]), "r"(bb[1]));
}

// ---------------------------------------------------------------------------
// Kernel 0: round fp32 -> tf32 (rna)
// ---------------------------------------------------------------------------
__global__ __launch_bounds__(256)
void round_tf32_kernel(const float* __restrict__ in, float* __restrict__ out, int n4)
{
    int i = blockIdx.x * blockDim.x + threadIdx.x;
    if (i >= n4) return;
    float4 v = ((const float4*)in)[i];
    uint32_t a, b, c, d;
    a = tf32_rna(v.x); b = tf32_rna(v.y); c = tf32_rna(v.z); d = tf32_rna(v.w);
    float4 o;
    o.x = __uint_as_float(a); o.y = __uint_as_float(b);
    o.z = __uint_as_float(c); o.w = __uint_as_float(d);
    ((float4*)out)[i] = o;
}

// ---------------------------------------------------------------------------
// Kernel 1: cp.async 3-stage pipelined tf32 HMMA GEMM
//   C = Xr @ Wr^T + b, fused activation -> g_act
//   256 threads = 8 warps in 2(M) x 4(N); warp tile 64x64 (4x8 m16n8k8 grid)
// ---------------------------------------------------------------------------
__global__ __launch_bounds__(256, 1)
void gemm_hmma_kernel(const float* __restrict__ b)
{
    extern __shared__ __align__(16) char smem[];
    const uint32_t sbase = smem_u32(smem);

    const int tid = threadIdx.x;
    const int wid = tid >> 5;
    const int lid = tid & 31;
    const int lq  = lid >> 2;   // 0..7
    const int lr  = lid & 3;    // 0..3

    const int wm = (wid >> 2) * 64;   // warp M offset: 0 / 64
    const int wn = (wid & 3) * 64;    // warp N offset: 0..192

    const int block_m = blockIdx.y * BM;
    const int block_n = blockIdx.x * BN;

    const float* Abase = g_Xr + (size_t)block_m * K_TOT;
    const float* Bbase = g_Wr + (size_t)block_n * K_TOT;

    // staging coords: A chunk = 1024 float4 (4/thread), B chunk = 2048 (8/thread)
    const int arow0 = tid >> 1;          // covers rows 0..127 for i=0,1 pattern below
    // we use pos = tid + i*256: row = pos>>3, c4 = pos&7

    float acc[4][8][4];
#pragma unroll
    for (int mt = 0; mt < 4; ++mt)
#pragma unroll
        for (int nt = 0; nt < 8; ++nt)
#pragma unroll
            for (int r = 0; r < 4; ++r) acc[mt][nt][r] = 0.0f;
    (void)arow0;

    // ---- prologue: issue loads for chunks 0..NSTAGE-2? (we issue 0..2) ----
#pragma unroll
    for (int p = 0; p < NSTAGE; ++p) {
        const int kcol = p * BK;
        const uint32_t a_s = sbase + p * A_STG_BYTES;
        const uint32_t b_s = sbase + SMEM_B_BASE + p * B_STG_BYTES;
#pragma unroll
        for (int i = 0; i < 4; ++i) {
            int pos = tid + i * 256;
            int r = pos >> 3, c4 = pos & 7;
            cp_async16(a_s + (uint32_t)(r * ASTRIDE + c4 * 4) * 4,
                       Abase + (size_t)r * K_TOT + kcol + c4 * 4);
        }
#pragma unroll
        for (int i = 0; i < 8; ++i) {
            int pos = tid + i * 256;
            int r = pos >> 3, c4 = pos & 7;
            cp_async16(b_s + (uint32_t)(r * ASTRIDE + c4 * 4) * 4,
                       Bbase + (size_t)r * K_TOT + kcol + c4 * 4);
        }
        cp_commit();
    }

    for (int c = 0; c < NCHUNK; ++c) {
        const int buf = c % NSTAGE;
        cp_wait<NSTAGE - 1>();
        __syncthreads();

        const uint32_t* As = (const uint32_t*)(smem + buf * A_STG_BYTES);
        const uint32_t* Bs = (const uint32_t*)(smem + SMEM_B_BASE + buf * B_STG_BYTES);

#pragma unroll
        for (int ks = 0; ks < 4; ++ks) {
            const int k0 = ks * 8;
            uint32_t afrag[4][4], bfrag[8][2];
#pragma unroll
            for (int mt = 0; mt < 4; ++mt) {
                int base = (wm + mt * 16 + lq) * ASTRIDE + k0 + lr;
                afrag[mt][0] = As[base];
                afrag[mt][1] = As[base + 8 * ASTRIDE];
                afrag[mt][2] = As[base + 4];
                afrag[mt][3] = As[base + 8 * ASTRIDE + 4];
            }
#pragma unroll
            for (int nt = 0; nt < 8; ++nt) {
                int base = (wn + nt * 8 + lq) * ASTRIDE + k0 + lr;
                bfrag[nt][0] = Bs[base];
                bfrag[nt][1] = Bs[base + 4];
            }
#pragma unroll
            for (int mt = 0; mt < 4; ++mt)
#pragma unroll
                for (int nt = 0; nt < 8; ++nt)
                    mma_tf32(acc[mt][nt], afrag[mt], bfrag[nt]);
        }

        __syncthreads();   // all warps done reading buf before refill

        if (c + NSTAGE < NCHUNK) {
            const int kcol = (c + NSTAGE) * BK;
            const uint32_t a_s = sbase + buf * A_STG_BYTES;
            const uint32_t b_s = sbase + SMEM_B_BASE + buf * B_STG_BYTES;
#pragma unroll
            for (int i = 0; i < 4; ++i) {
                int pos = tid + i * 256;
                int r = pos >> 3, c4 = pos & 7;
                cp_async16(a_s + (uint32_t)(r * ASTRIDE + c4 * 4) * 4,
                           Abase + (size_t)r * K_TOT + kcol + c4 * 4);
            }
#pragma unroll
            for (int i = 0; i < 8; ++i) {
                int pos = tid + i * 256;
                int r = pos >> 3, c4 = pos & 7;
                cp_async16(b_s + (uint32_t)(r * ASTRIDE + c4 * 4) * 4,
                           Bbase + (size_t)r * K_TOT + kcol + c4 * 4);
            }
        }
        cp_commit();   // commit every iteration to keep group accounting uniform
    }

    // ---- epilogue: bias + activation -> g_act ----
    const bool is_tanh = (block_n < DIM);   // BN=256 divides DIM

#pragma unroll
    for (int nt = 0; nt < 8; ++nt) {
        const int gc = block_n + wn + nt * 8 + 2 * lr;
        const float b0 = __ldg(&b[gc]);
        const float b1 = __ldg(&b[gc + 1]);
#pragma unroll
        for (int mt = 0; mt < 4; ++mt) {
            const int gm0 = block_m + wm + mt * 16 + lq;
            const int gm1 = gm0 + 8;
            float v00 = acc[mt][nt][0] + b0;
            float v01 = acc[mt][nt][1] + b1;
            float v10 = acc[mt][nt][2] + b0;
            float v11 = acc[mt][nt][3] + b1;
            float2 r0, r1;
            if (is_tanh) {
                r0.x = tanh_f(v00); r0.y = tanh_f(v01);
                r1.x = tanh_f(v10); r1.y = tanh_f(v11);
            } else {
                r0.x = sigmoid_f(v00); r0.y = sigmoid_f(v01);
                r1.x = sigmoid_f(v10); r1.y = sigmoid_f(v11);
            }
            *(float2*)(&g_act[(size_t)gm0 * N_TOT + gc]) = r0;
            *(float2*)(&g_act[(size_t)gm1 * N_TOT + gc]) = r1;
        }
    }
}

// ---------------------------------------------------------------------------
// Kernel 2: sequential scan (256 CTAs x 128 threads so all SMs get work)
// ---------------------------------------------------------------------------
__global__ __launch_bounds__(128)
void scan_kernel(const float* __restrict__ hidden, float* __restrict__ out)
{
    const int t = blockIdx.x * blockDim.x + threadIdx.x;  // 0..32767
    const int bb = t >> 10;
    const int d  = t & 1023;

    float h = hidden[bb * DIM + d];

    float* __restrict__ Hout = out;
    float* __restrict__ hn   = out + (size_t)SEQ * BATCH * DIM;

#pragma unroll 8
    for (int s = 0; s < SEQ; ++s) {
        const size_t row = (size_t)(s * BATCH + bb) * N_TOT;
        const float z = g_act[row + d];
        const float f = g_act[row + DIM + d];
        const float o = g_act[row + 2 * DIM + d];
        h = fmaf(f, h - z, z);
        Hout[(size_t)(s * BATCH + bb) * DIM + d] = o * h;
    }
    hn[bb * DIM + d] = h;
}

// ---------------------------------------------------------------------------
extern "C" void kernel_launch(void* const* d_in, const int* in_sizes, int n_in,
                              void* d_out, int out_size)
{
    const float* X      = (const float*)d_in[0];   // [2048, 32, 1024]
    const float* hidden = (const float*)d_in[1];   // [1, 32, 1024]
    const float* W      = (const float*)d_in[2];   // [3072, 1024]
    const float* b      = (const float*)d_in[3];   // [3072]
    float* out = (float*)d_out;

    cudaFuncSetAttribute(gemm_hmma_kernel,
                         cudaFuncAttributeMaxDynamicSharedMemorySize,
                         SMEM_BYTES);

    float* Xr; float* Wr;
    cudaGetSymbolAddress((void**)&Xr, g_Xr);
    cudaGetSymbolAddress((void**)&Wr, g_Wr);

    // round inputs to tf32 (rna)
    {
        int n4x = (M_TOT * K_TOT) / 4;
        round_tf32_kernel<<<n4x / 256, 256>>>(X, Xr, n4x);
        int n4w = (N_TOT * K_TOT) / 4;
        round_tf32_kernel<<<n4w / 256, 256>>>(W, Wr, n4w);
    }

    dim3 grid(N_TOT / BN, M_TOT / BM);   // (12, 512)
    gemm_hmma_kernel<<<grid, 256, SMEM_BYTES>>>(b);

    scan_kernel<<<(BATCH * DIM) / 128, 128>>>(hidden, out);
}